// round 12
// baseline (speedup 1.0000x reference)
#include <cuda_runtime.h>
#include <cuda_fp16.h>
#include <cstdint>

#define NB     8
#define S_ENC  256
#define S_DEC  128
#define DIM    512     // D_ENC = D_DEC = UNITS = 512

// Scratch (no cudaMalloc allowed)
__device__ __half g_denc_h[NB * S_ENC * DIM];   // [B, S_ENC, U] f16
__device__ float  g_ddec[NB * S_DEC * DIM];     // [B, S_DEC, U] f32

// ---------------------------------------------------------------------------
// tf32 tensor-core GEMM (3xTF32 split -> fp32-level accuracy).
//   z=0 : d_enc = enc @ W_enc + b_enc   (M=2048) -> written as f16
//   z=1 : d_dec = dec @ W_dec + b_dec   (M=1024) -> written as f32
// ---------------------------------------------------------------------------
#define TBM 64
#define TBN 64
#define TBK 32
#define ASTR 36
#define BSTR 72
#define NC  (DIM / TBK)

__device__ __forceinline__ uint32_t f2tf32(float x) {
    uint32_t u;
    asm("cvt.rna.tf32.f32 %0, %1;" : "=r"(u) : "f"(x));
    return u;
}
__device__ __forceinline__ void split_tf32(float x, uint32_t& hi, uint32_t& lo) {
    hi = f2tf32(x);
    lo = f2tf32(x - __uint_as_float(hi));
}
__device__ __forceinline__ void mma_tf32(float c[4], const uint32_t a[4],
                                         const uint32_t b[2]) {
    asm volatile(
        "mma.sync.aligned.m16n8k8.row.col.f32.tf32.tf32.f32 "
        "{%0,%1,%2,%3}, {%4,%5,%6,%7}, {%8,%9}, {%0,%1,%2,%3};"
        : "+f"(c[0]), "+f"(c[1]), "+f"(c[2]), "+f"(c[3])
        : "r"(a[0]), "r"(a[1]), "r"(a[2]), "r"(a[3]), "r"(b[0]), "r"(b[1]));
}

__global__ __launch_bounds__(128) void gemm_tf32_kernel(
    const float* __restrict__ Xe, const float* __restrict__ We,
    const float* __restrict__ be, __half* __restrict__ Ceh,
    const float* __restrict__ Xd, const float* __restrict__ Wd,
    const float* __restrict__ bd, float* __restrict__ Cd)
{
    const int z = blockIdx.z;
    if (z == 1 && blockIdx.y >= (NB * S_DEC) / TBM) return;

    const float* __restrict__ X    = z ? Xd : Xe;
    const float* __restrict__ W    = z ? Wd : We;
    const float* __restrict__ bias = z ? bd : be;

    __shared__ float As[2][TBM * ASTR];
    __shared__ float Bs[2][TBK * BSTR];
    __shared__ float bsm[TBN];

    const int tid  = threadIdx.x;
    const int lane = tid & 31;
    const int warp = tid >> 5;
    const int wm   = warp >> 1;
    const int wn   = warp & 1;
    const int row0 = blockIdx.y * TBM;
    const int col0 = blockIdx.x * TBN;

    if (tid < TBN) bsm[tid] = bias[col0 + tid];

    #define ISSUE_GEMM_CHUNK(ch, st)                                           \
        do {                                                                   \
            const int k0 = (ch) * TBK;                                         \
            _Pragma("unroll")                                                  \
            for (int j = 0; j < 4; j++) {                                      \
                const int idx = j * 128 + tid;                                 \
                const int r = idx >> 3, c = (idx & 7) * 4;                     \
                const unsigned dst = (unsigned)__cvta_generic_to_shared(       \
                    &As[st][r * ASTR + c]);                                    \
                const float* src = &X[(row0 + r) * DIM + k0 + c];              \
                asm volatile("cp.async.cg.shared.global [%0], [%1], 16;\n"     \
                             :: "r"(dst), "l"(src));                           \
            }                                                                  \
            _Pragma("unroll")                                                  \
            for (int j = 0; j < 4; j++) {                                      \
                const int idx = j * 128 + tid;                                 \
                const int r = idx >> 4, c = (idx & 15) * 4;                    \
                const unsigned dst = (unsigned)__cvta_generic_to_shared(       \
                    &Bs[st][r * BSTR + c]);                                    \
                const float* src = &W[(k0 + r) * DIM + col0 + c];              \
                asm volatile("cp.async.cg.shared.global [%0], [%1], 16;\n"     \
                             :: "r"(dst), "l"(src));                           \
            }                                                                  \
            asm volatile("cp.async.commit_group;\n");                          \
        } while (0)

    float acc[2][4][4] = {};

    ISSUE_GEMM_CHUNK(0, 0);
    ISSUE_GEMM_CHUNK(1, 1);
    asm volatile("cp.async.wait_group 1;\n");
    __syncthreads();

    for (int ch = 0; ch < NC; ch++) {
        const int st = ch & 1;
        const float* A = As[st];
        const float* B = Bs[st];

        #pragma unroll
        for (int ks = 0; ks < TBK / 8; ks++) {
            const int k = ks * 8;
            uint32_t ahi[2][4], alo[2][4];
            #pragma unroll
            for (int mt = 0; mt < 2; mt++) {
                const int m = wm * 32 + mt * 16;
                const int r = m + (lane >> 2);
                const int c = k + (lane & 3);
                split_tf32(A[r * ASTR + c],           ahi[mt][0], alo[mt][0]);
                split_tf32(A[(r + 8) * ASTR + c],     ahi[mt][1], alo[mt][1]);
                split_tf32(A[r * ASTR + c + 4],       ahi[mt][2], alo[mt][2]);
                split_tf32(A[(r + 8) * ASTR + c + 4], ahi[mt][3], alo[mt][3]);
            }
            uint32_t bhi[4][2], blo[4][2];
            #pragma unroll
            for (int nt = 0; nt < 4; nt++) {
                const int n = wn * 32 + nt * 8 + (lane >> 2);
                const int r = k + (lane & 3);
                split_tf32(B[r * BSTR + n],       bhi[nt][0], blo[nt][0]);
                split_tf32(B[(r + 4) * BSTR + n], bhi[nt][1], blo[nt][1]);
            }
            #pragma unroll
            for (int mt = 0; mt < 2; mt++)
                #pragma unroll
                for (int nt = 0; nt < 4; nt++) {
                    mma_tf32(acc[mt][nt], ahi[mt], bhi[nt]);
                    mma_tf32(acc[mt][nt], ahi[mt], blo[nt]);
                    mma_tf32(acc[mt][nt], alo[mt], bhi[nt]);
                }
        }

        __syncthreads();
        if (ch + 2 < NC) {
            ISSUE_GEMM_CHUNK(ch + 2, st);
            asm volatile("cp.async.wait_group 1;\n");
            __syncthreads();
        } else if (ch + 1 < NC) {
            asm volatile("cp.async.wait_group 0;\n");
            __syncthreads();
        }
    }

    // ---- epilogue: bias + store (z=0 -> f16 pairs, z=1 -> f32 pairs) ------
    #pragma unroll
    for (int mt = 0; mt < 2; mt++) {
        const int r = row0 + wm * 32 + mt * 16 + (lane >> 2);
        #pragma unroll
        for (int nt = 0; nt < 4; nt++) {
            const int cl = wn * 32 + nt * 8 + (lane & 3) * 2;
            const float b0 = bsm[cl], b1 = bsm[cl + 1];
            const float v00 = acc[mt][nt][0] + b0, v01 = acc[mt][nt][1] + b1;
            const float v10 = acc[mt][nt][2] + b0, v11 = acc[mt][nt][3] + b1;
            if (z == 0) {
                *(__half2*)&Ceh[r * DIM + col0 + cl] =
                    __floats2half2_rn(v00, v01);
                *(__half2*)&Ceh[(r + 8) * DIM + col0 + cl] =
                    __floats2half2_rn(v10, v11);
            } else {
                *(float2*)&Cd[r * DIM + col0 + cl]       = make_float2(v00, v01);
                *(float2*)&Cd[(r + 8) * DIM + col0 + cl] = make_float2(v10, v11);
            }
        }
    }
}

// ---------------------------------------------------------------------------
// Attention kernel. Block = (batch b, QT=8 q's), 1024 threads = 32 warps.
// Warp w -> (q = w>>2, u-quarter = w&3); lane owns 4 contiguous u.
// d_enc arrives as f16 (GEMM epilogue); inner loop per e is 8 instructions:
// LDS.64 -> 2 HADD2 -> 2 tanh.approx.f16x2 -> HMUL2 + HFMA2. Accumulators
// stay PACKED (f16x2) through the first two butterfly stages (HADD2, small
// magnitudes -> negligible rounding); only 4 unpacks per chunk, then the
// tail of the reduction runs in f32.
// ---------------------------------------------------------------------------
#define QT   8
#define EB   16                  // encoder rows per chunk
#define NCH  (S_ENC / EB)        // 16
#define ATH  1024
#define CHB  (EB * DIM * 2)      // 16384 bytes per chunk (f16)

__device__ __forceinline__ __half2 tanh2h(__half2 x) {
    uint32_t u = *reinterpret_cast<uint32_t*>(&x);
    asm("tanh.approx.f16x2 %0, %0;" : "+r"(u));
    return *reinterpret_cast<__half2*>(&u);
}
__device__ __forceinline__ __half2 shfl_h2(__half2 v, int s) {
    uint32_t u = *reinterpret_cast<uint32_t*>(&v);
    u = __shfl_xor_sync(0xFFFFFFFFu, u, s);
    return *reinterpret_cast<__half2*>(&u);
}

__global__ __launch_bounds__(ATH, 1) void attn_kernel(
    const float* __restrict__ enc,      // [B, S_ENC, DIM] raw encodings
    const float* __restrict__ wscore,   // [DIM]
    const float* __restrict__ bscore,   // [1]
    float* __restrict__ out)            // [B, S_DEC, DIM]
{
    extern __shared__ __align__(16) unsigned char smem_raw[];
    __half* s_deh = (__half*)smem_raw;                       // 2*CHB = 32768 B
    float* s_part = (float*)(smem_raw + 2 * CHB);            // 32*S_ENC f
    float* s_sc   = s_part + 32 * S_ENC;                     // QT*S_ENC f
    float* s_t    = s_sc + QT * S_ENC;                       // S_ENC*QT f

    const int b    = blockIdx.y;
    const int q0   = blockIdx.x * QT;
    const int tid  = threadIdx.x;
    const int lane = tid & 31;
    const int w    = tid >> 5;
    const int q    = w >> 2;            // local q in [0,8)
    const int quad = w & 3;             // u-quarter
    const int u0   = quad * 128 + lane * 4;   // 4 contiguous u per lane

    // ---- loop-invariant registers (all f16x2) -----------------------------
    __half2 dd01, dd23, w01h, w23h;
    {
        const float* ddp = g_ddec + (b * S_DEC + q0 + q) * DIM;
        const float4 dv = *(const float4*)&ddp[u0];
        dd01 = __floats2half2_rn(dv.x, dv.y);
        dd23 = __floats2half2_rn(dv.z, dv.w);
        const float4 wv = *(const float4*)&wscore[u0];
        w01h = __floats2half2_rn(wv.x, wv.y);
        w23h = __floats2half2_rn(wv.z, wv.w);
    }

    const float4* gsrc = (const float4*)(g_denc_h + b * S_ENC * DIM);
    const unsigned sde_base = (unsigned)__cvta_generic_to_shared(s_deh);

    // chunk = 1024 float4 of f16 data; exactly one 16B cp.async per thread
    #define ISSUE_CHUNK(ch, buf)                                               \
        do {                                                                   \
            const unsigned dst = sde_base + (buf) * CHB + tid * 16u;           \
            const float4* srcp = gsrc + (ch) * (CHB / 16) + tid;               \
            asm volatile("cp.async.cg.shared.global [%0], [%1], 16;\n"         \
                         :: "r"(dst), "l"(srcp));                              \
            asm volatile("cp.async.commit_group;\n");                          \
        } while (0)

    ISSUE_CHUNK(0, 0);
    ISSUE_CHUNK(1, 1);
    asm volatile("cp.async.wait_group 1;\n");
    __syncthreads();

    // ---- score chunks ------------------------------------------------------
    for (int ch = 0; ch < NCH; ch++) {
        const uint2* de2 = (const uint2*)(s_deh + (ch & 1) * EB * DIM) +
                           (u0 >> 2);

        __half2 acc[EB];
        #pragma unroll
        for (int e = 0; e < EB; e++) {
            const uint2 ev = de2[e * (DIM / 4)];
            const __half2 x01 = __hadd2(dd01, *(const __half2*)&ev.x);
            const __half2 x23 = __hadd2(dd23, *(const __half2*)&ev.y);
            const __half2 t01 = tanh2h(x01);
            const __half2 t23 = tanh2h(x23);
            acc[e] = __hfma2(t23, w23h, __hmul2(t01, w01h));
        }

        // packed butterfly: stages s=16 (n=8), s=8 (n=4) in HADD2
        #pragma unroll
        for (int s = 16, n = 8; s >= 8; s >>= 1, n >>= 1) {
            const bool hi = (lane & s) != 0;
            #pragma unroll
            for (int j = 0; j < n; j++) {
                const __half2 send = hi ? acc[j] : acc[j + n];
                const __half2 keep = hi ? acc[j + n] : acc[j];
                acc[j] = __hadd2(keep, shfl_h2(send, s));
            }
        }
        // unpack the 4 survivors to f32 (lo+hi completes the u-pair sum)
        float fac[4];
        #pragma unroll
        for (int j = 0; j < 4; j++)
            fac[j] = __low2float(acc[j]) + __high2float(acc[j]);
        // f32 tail: stages s=4 (n=2), s=2 (n=1), then s=1
        #pragma unroll
        for (int s = 4, n = 2; s >= 2; s >>= 1, n >>= 1) {
            const bool hi = (lane & s) != 0;
            #pragma unroll
            for (int j = 0; j < n; j++) {
                const float send = hi ? fac[j] : fac[j + n];
                const float keep = hi ? fac[j + n] : fac[j];
                fac[j] = keep + __shfl_xor_sync(0xFFFFFFFFu, send, s);
            }
        }
        fac[0] += __shfl_xor_sync(0xFFFFFFFFu, fac[0], 1);
        if ((lane & 1) == 0)
            s_part[w * S_ENC + ch * EB + ((lane >> 1) & 15)] = fac[0];

        if (ch + 1 < NCH) {
            __syncthreads();                       // done reading buf[ch&1]
            if (ch + 2 < NCH) {
                ISSUE_CHUNK(ch + 2, (ch & 1));
                asm volatile("cp.async.wait_group 1;\n");
            } else {
                asm volatile("cp.async.wait_group 0;\n");
            }
            __syncthreads();                       // new buffer visible
        }
    }
    __syncthreads();   // all s_part written

    // ---- combine quarter-sums + bias --------------------------------------
    const float bsc = bscore[0];
    for (int idx = tid; idx < QT * S_ENC; idx += ATH) {
        const int qq = idx >> 8, e = idx & (S_ENC - 1);
        s_sc[qq * S_ENC + e] =
            s_part[(4 * qq + 0) * S_ENC + e] + s_part[(4 * qq + 1) * S_ENC + e] +
            s_part[(4 * qq + 2) * S_ENC + e] + s_part[(4 * qq + 3) * S_ENC + e] + bsc;
    }
    __syncthreads();

    // ---- softmax (warps 0-7 handle q=w); write transposed [e][q] ----------
    if (w < QT) {
        float v[S_ENC / 32];
        float m = -1e30f;
        #pragma unroll
        for (int i = 0; i < S_ENC / 32; i++) {
            v[i] = s_sc[w * S_ENC + lane + 32 * i];
            m = fmaxf(m, v[i]);
        }
        #pragma unroll
        for (int off = 16; off; off >>= 1)
            m = fmaxf(m, __shfl_xor_sync(0xFFFFFFFFu, m, off));
        float sum = 0.f;
        #pragma unroll
        for (int i = 0; i < S_ENC / 32; i++) {
            v[i] = __expf(v[i] - m);
            sum += v[i];
        }
        #pragma unroll
        for (int off = 16; off; off >>= 1)
            sum += __shfl_xor_sync(0xFFFFFFFFu, sum, off);
        const float inv = 1.f / sum;
        #pragma unroll
        for (int i = 0; i < S_ENC / 32; i++)
            s_t[(lane + 32 * i) * QT + w] = v[i] * inv;
    }
    __syncthreads();

    // ---- context: warp w owns dims [w*16, w*16+16); half-warps split e ----
    const int dl = lane & 15;
    const int eh = lane >> 4;           // 0/1 -> e-half
    const int d0 = w * 16 + dl;
    float c[QT] = {};
    const float* ep = enc + b * S_ENC * DIM;

    const int e_beg = eh * 128;
    #pragma unroll 4
    for (int e = e_beg; e < e_beg + 128; e++) {
        const float ev = ep[e * DIM + d0];
        const float4 w0 = *(const float4*)&s_t[e * QT];       // broadcast
        const float4 w1 = *(const float4*)&s_t[e * QT + 4];
        c[0] = fmaf(w0.x, ev, c[0]);
        c[1] = fmaf(w0.y, ev, c[1]);
        c[2] = fmaf(w0.z, ev, c[2]);
        c[3] = fmaf(w0.w, ev, c[3]);
        c[4] = fmaf(w1.x, ev, c[4]);
        c[5] = fmaf(w1.y, ev, c[5]);
        c[6] = fmaf(w1.z, ev, c[6]);
        c[7] = fmaf(w1.w, ev, c[7]);
    }
    #pragma unroll
    for (int qq = 0; qq < QT; qq++)
        c[qq] += __shfl_xor_sync(0xFFFFFFFFu, c[qq], 16);

    if (lane < 16) {
        #pragma unroll
        for (int qq = 0; qq < QT; qq++)
            out[(b * S_DEC + q0 + qq) * DIM + d0] = c[qq];
    }
}

#define ATTN_SMEM (2 * CHB + (32 * S_ENC + 2 * QT * S_ENC) * (int)sizeof(float))

// ---------------------------------------------------------------------------
extern "C" void kernel_launch(void* const* d_in, const int* in_sizes, int n_in,
                              void* d_out, int out_size)
{
    const float* encodings = (const float*)d_in[0];   // [8,256,512]
    const float* decodings = (const float*)d_in[1];   // [8,128,512]
    const float* W_enc     = (const float*)d_in[2];   // [512,512]
    const float* W_dec     = (const float*)d_in[3];   // [512,512]
    const float* W_score   = (const float*)d_in[4];   // [512,1]
    const float* bias_enc  = (const float*)d_in[5];   // [512]
    const float* bias_dec  = (const float*)d_in[6];   // [512]
    const float* bias_sc   = (const float*)d_in[7];   // [1]
    float* out = (float*)d_out;                       // [8,128,512]

    void* p_dench = nullptr;
    void* p_ddec  = nullptr;
    cudaGetSymbolAddress(&p_dench, g_denc_h);
    cudaGetSymbolAddress(&p_ddec, g_ddec);

    cudaFuncSetAttribute(attn_kernel,
                         cudaFuncAttributeMaxDynamicSharedMemorySize, ATTN_SMEM);

    // both projections in one tensor-core launch (z selects enc/dec)
    {
        dim3 grid(DIM / TBN, (NB * S_ENC) / TBM, 2);   // (8, 32, 2)
        gemm_tf32_kernel<<<grid, 128>>>(encodings, W_enc, bias_enc,
                                        (__half*)p_dench,
                                        decodings, W_dec, bias_dec,
                                        (float*)p_ddec);
    }

    // scores + softmax + context
    {
        dim3 grid(S_DEC / QT, NB);                     // (16, 8)
        attn_kernel<<<grid, ATH, ATTN_SMEM>>>(encodings, W_score, bias_sc, out);
    }
}

// round 13
// speedup vs baseline: 1.1539x; 1.1539x over previous
#include <cuda_runtime.h>
#include <cstdint>

#define NB     8
#define S_ENC  256
#define S_DEC  128
#define DIM    512     // D_ENC = D_DEC = UNITS = 512

// Scratch (no cudaMalloc allowed): tanh-transformed projections
__device__ float g_tenc[NB * S_ENC * DIM];   // tanh(enc @ W_enc + b_enc)
__device__ float g_tdec[NB * S_DEC * DIM];   // tanh(dec @ W_dec + b_dec)

__device__ __forceinline__ float tanh_approx(float x) {
    float y;
    asm("tanh.approx.f32 %0, %1;" : "=f"(y) : "f"(x));
    return y;
}

// ---------------------------------------------------------------------------
// tf32 tensor-core GEMM (3xTF32 split -> fp32-level accuracy).
//   z=0 : tanh(enc @ W_enc + b_enc)   (M=2048)
//   z=1 : tanh(dec @ W_dec + b_dec)   (M=1024)
// Epilogue applies tanh so the attention loop can use the tanh addition
// formula: tanh(a+b) = (ta + tb) / (1 + ta*tb)  -- RCP (rt8) replaces the
// per-element tanh (rt16), halving XU-pipe time in the hot loop.
// ---------------------------------------------------------------------------
#define TBM 64
#define TBN 64
#define TBK 32
#define ASTR 36
#define BSTR 72
#define NC  (DIM / TBK)

__device__ __forceinline__ uint32_t f2tf32(float x) {
    uint32_t u;
    asm("cvt.rna.tf32.f32 %0, %1;" : "=r"(u) : "f"(x));
    return u;
}
__device__ __forceinline__ void split_tf32(float x, uint32_t& hi, uint32_t& lo) {
    hi = f2tf32(x);
    lo = f2tf32(x - __uint_as_float(hi));
}
__device__ __forceinline__ void mma_tf32(float c[4], const uint32_t a[4],
                                         const uint32_t b[2]) {
    asm volatile(
        "mma.sync.aligned.m16n8k8.row.col.f32.tf32.tf32.f32 "
        "{%0,%1,%2,%3}, {%4,%5,%6,%7}, {%8,%9}, {%0,%1,%2,%3};"
        : "+f"(c[0]), "+f"(c[1]), "+f"(c[2]), "+f"(c[3])
        : "r"(a[0]), "r"(a[1]), "r"(a[2]), "r"(a[3]), "r"(b[0]), "r"(b[1]));
}

__global__ __launch_bounds__(128) void gemm_tf32_kernel(
    const float* __restrict__ Xe, const float* __restrict__ We,
    const float* __restrict__ be, float* __restrict__ Ce,
    const float* __restrict__ Xd, const float* __restrict__ Wd,
    const float* __restrict__ bd, float* __restrict__ Cd)
{
    const int z = blockIdx.z;
    if (z == 1 && blockIdx.y >= (NB * S_DEC) / TBM) return;

    const float* __restrict__ X    = z ? Xd : Xe;
    const float* __restrict__ W    = z ? Wd : We;
    const float* __restrict__ bias = z ? bd : be;
    float* __restrict__ C          = z ? Cd : Ce;

    __shared__ float As[2][TBM * ASTR];
    __shared__ float Bs[2][TBK * BSTR];
    __shared__ float bsm[TBN];

    const int tid  = threadIdx.x;
    const int lane = tid & 31;
    const int warp = tid >> 5;
    const int wm   = warp >> 1;
    const int wn   = warp & 1;
    const int row0 = blockIdx.y * TBM;
    const int col0 = blockIdx.x * TBN;

    if (tid < TBN) bsm[tid] = bias[col0 + tid];

    #define ISSUE_GEMM_CHUNK(ch, st)                                           \
        do {                                                                   \
            const int k0 = (ch) * TBK;                                         \
            _Pragma("unroll")                                                  \
            for (int j = 0; j < 4; j++) {                                      \
                const int idx = j * 128 + tid;                                 \
                const int r = idx >> 3, c = (idx & 7) * 4;                     \
                const unsigned dst = (unsigned)__cvta_generic_to_shared(       \
                    &As[st][r * ASTR + c]);                                    \
                const float* src = &X[(row0 + r) * DIM + k0 + c];              \
                asm volatile("cp.async.cg.shared.global [%0], [%1], 16;\n"     \
                             :: "r"(dst), "l"(src));                           \
            }                                                                  \
            _Pragma("unroll")                                                  \
            for (int j = 0; j < 4; j++) {                                      \
                const int idx = j * 128 + tid;                                 \
                const int r = idx >> 4, c = (idx & 15) * 4;                    \
                const unsigned dst = (unsigned)__cvta_generic_to_shared(       \
                    &Bs[st][r * BSTR + c]);                                    \
                const float* src = &W[(k0 + r) * DIM + col0 + c];              \
                asm volatile("cp.async.cg.shared.global [%0], [%1], 16;\n"     \
                             :: "r"(dst), "l"(src));                           \
            }                                                                  \
            asm volatile("cp.async.commit_group;\n");                          \
        } while (0)

    float acc[2][4][4] = {};

    ISSUE_GEMM_CHUNK(0, 0);
    ISSUE_GEMM_CHUNK(1, 1);
    asm volatile("cp.async.wait_group 1;\n");
    __syncthreads();

    for (int ch = 0; ch < NC; ch++) {
        const int st = ch & 1;
        const float* A = As[st];
        const float* B = Bs[st];

        #pragma unroll
        for (int ks = 0; ks < TBK / 8; ks++) {
            const int k = ks * 8;
            uint32_t ahi[2][4], alo[2][4];
            #pragma unroll
            for (int mt = 0; mt < 2; mt++) {
                const int m = wm * 32 + mt * 16;
                const int r = m + (lane >> 2);
                const int c = k + (lane & 3);
                split_tf32(A[r * ASTR + c],           ahi[mt][0], alo[mt][0]);
                split_tf32(A[(r + 8) * ASTR + c],     ahi[mt][1], alo[mt][1]);
                split_tf32(A[r * ASTR + c + 4],       ahi[mt][2], alo[mt][2]);
                split_tf32(A[(r + 8) * ASTR + c + 4], ahi[mt][3], alo[mt][3]);
            }
            uint32_t bhi[4][2], blo[4][2];
            #pragma unroll
            for (int nt = 0; nt < 4; nt++) {
                const int n = wn * 32 + nt * 8 + (lane >> 2);
                const int r = k + (lane & 3);
                split_tf32(B[r * BSTR + n],       bhi[nt][0], blo[nt][0]);
                split_tf32(B[(r + 4) * BSTR + n], bhi[nt][1], blo[nt][1]);
            }
            #pragma unroll
            for (int mt = 0; mt < 2; mt++)
                #pragma unroll
                for (int nt = 0; nt < 4; nt++) {
                    mma_tf32(acc[mt][nt], ahi[mt], bhi[nt]);
                    mma_tf32(acc[mt][nt], ahi[mt], blo[nt]);
                    mma_tf32(acc[mt][nt], alo[mt], bhi[nt]);
                }
        }

        __syncthreads();
        if (ch + 2 < NC) {
            ISSUE_GEMM_CHUNK(ch + 2, st);
            asm volatile("cp.async.wait_group 1;\n");
            __syncthreads();
        } else if (ch + 1 < NC) {
            asm volatile("cp.async.wait_group 0;\n");
            __syncthreads();
        }
    }

    // ---- epilogue: bias + tanh + store ------------------------------------
    #pragma unroll
    for (int mt = 0; mt < 2; mt++) {
        const int r = row0 + wm * 32 + mt * 16 + (lane >> 2);
        #pragma unroll
        for (int nt = 0; nt < 4; nt++) {
            const int cl = wn * 32 + nt * 8 + (lane & 3) * 2;
            const float b0 = bsm[cl], b1 = bsm[cl + 1];
            float2 v0 = {tanh_approx(acc[mt][nt][0] + b0),
                         tanh_approx(acc[mt][nt][1] + b1)};
            float2 v1 = {tanh_approx(acc[mt][nt][2] + b0),
                         tanh_approx(acc[mt][nt][3] + b1)};
            *(float2*)&C[r * DIM + col0 + cl]       = v0;
            *(float2*)&C[(r + 8) * DIM + col0 + cl] = v1;
        }
    }
}

// ---------------------------------------------------------------------------
// Attention kernel. Block = (batch b, QT=8 q's), 1024 threads = 32 warps.
// Warp w -> (q = w>>2, u-quarter = w&3); lane owns 4 contiguous u
// (one LDS.128 per e). Inner loop uses the tanh addition formula:
//   tanh(dd+de) = (td+te) / (1 + td*te),  td/te precomputed by the GEMM.
// Per u: FADD + FFMA + RCP(rt8) + FMUL + FFMA -- no tanh in the hot loop.
// ---------------------------------------------------------------------------
#define QT   8
#define EB   16                  // encoder rows per chunk
#define NCH  (S_ENC / EB)        // 16
#define ATH  1024
#define CHV  (EB * DIM / 4)      // 2048 float4 per chunk
#define PFT  (CHV / ATH)         // 2 float4 per thread

__global__ __launch_bounds__(ATH, 1) void attn_kernel(
    const float* __restrict__ enc,      // [B, S_ENC, DIM] raw encodings
    const float* __restrict__ wscore,   // [DIM]
    const float* __restrict__ bscore,   // [1]
    float* __restrict__ out)            // [B, S_DEC, DIM]
{
    extern __shared__ float smem[];
    float* s_de   = smem;                         // 2*EB*DIM   (16384 f)
    float* s_part = s_de + 2 * EB * DIM;          // 32*S_ENC   (8192 f)
    float* s_sc   = s_part + 32 * S_ENC;          // QT*S_ENC   (2048 f)
    float* s_t    = s_sc + QT * S_ENC;            // S_ENC*QT   (2048 f)

    const int b    = blockIdx.y;
    const int q0   = blockIdx.x * QT;
    const int tid  = threadIdx.x;
    const int lane = tid & 31;
    const int w    = tid >> 5;
    const int q    = w >> 2;            // local q in [0,8)
    const int quad = w & 3;             // u-quarter
    const int u0   = quad * 128 + lane * 4;   // 4 contiguous u per lane

    // ---- loop-invariant registers -----------------------------------------
    float4 td;           // tanh(d_dec) slice
    float4 ws;           // W_score slice
    {
        const float* tdp = g_tdec + (b * S_DEC + q0 + q) * DIM;
        td = *(const float4*)&tdp[u0];
        ws = *(const float4*)&wscore[u0];
    }

    const float4* gsrc = (const float4*)(g_tenc + b * S_ENC * DIM);
    const unsigned sde_base = (unsigned)__cvta_generic_to_shared(s_de);

    #define ISSUE_CHUNK(ch, buf)                                               \
        do {                                                                   \
            _Pragma("unroll")                                                  \
            for (int j = 0; j < PFT; j++) {                                    \
                const int idx = j * ATH + tid;                                 \
                const unsigned dst = sde_base + ((buf) * CHV + idx) * 16u;     \
                const float4* srcp = gsrc + (ch) * CHV + idx;                  \
                asm volatile("cp.async.cg.shared.global [%0], [%1], 16;\n"     \
                             :: "r"(dst), "l"(srcp));                          \
            }                                                                  \
            asm volatile("cp.async.commit_group;\n");                          \
        } while (0)

    ISSUE_CHUNK(0, 0);
    ISSUE_CHUNK(1, 1);
    asm volatile("cp.async.wait_group 1;\n");
    __syncthreads();

    // ---- score chunks ------------------------------------------------------
    for (int ch = 0; ch < NCH; ch++) {
        const float4* de4 = (const float4*)(s_de + (ch & 1) * EB * DIM) +
                            (u0 >> 2);

        float acc[EB];
        #pragma unroll
        for (int e = 0; e < EB; e++) {
            const float4 te = de4[e * (DIM / 4)];
            // tanh addition formula, RCP instead of tanh in the hot loop
            const float n0 = td.x + te.x, d0 = fmaf(td.x, te.x, 1.f);
            const float n1 = td.y + te.y, d1 = fmaf(td.y, te.y, 1.f);
            const float n2 = td.z + te.z, d2 = fmaf(td.z, te.z, 1.f);
            const float n3 = td.w + te.w, d3 = fmaf(td.w, te.w, 1.f);
            float r0, r1, r2, r3;
            asm("rcp.approx.f32 %0, %1;" : "=f"(r0) : "f"(d0));
            asm("rcp.approx.f32 %0, %1;" : "=f"(r1) : "f"(d1));
            asm("rcp.approx.f32 %0, %1;" : "=f"(r2) : "f"(d2));
            asm("rcp.approx.f32 %0, %1;" : "=f"(r3) : "f"(d3));
            float s;
            s = (n0 * r0) * ws.x;
            s = fmaf(n1 * r1, ws.y, s);
            s = fmaf(n2 * r2, ws.z, s);
            s = fmaf(n3 * r3, ws.w, s);
            acc[e] = s;
        }

        // multi-value butterfly: fold 16 values over stages s=16..2, then s=1
        #pragma unroll
        for (int s = 16, n = 8; s >= 2; s >>= 1, n >>= 1) {
            const bool hi = (lane & s) != 0;
            #pragma unroll
            for (int j = 0; j < n; j++) {
                const float send = hi ? acc[j] : acc[j + n];
                const float keep = hi ? acc[j + n] : acc[j];
                acc[j] = keep + __shfl_xor_sync(0xFFFFFFFFu, send, s);
            }
        }
        acc[0] += __shfl_xor_sync(0xFFFFFFFFu, acc[0], 1);
        if ((lane & 1) == 0)
            s_part[w * S_ENC + ch * EB + ((lane >> 1) & 15)] = acc[0];

        if (ch + 1 < NCH) {
            __syncthreads();                       // done reading buf[ch&1]
            if (ch + 2 < NCH) {
                ISSUE_CHUNK(ch + 2, (ch & 1));
                asm volatile("cp.async.wait_group 1;\n");
            } else {
                asm volatile("cp.async.wait_group 0;\n");
            }
            __syncthreads();                       // new buffer visible
        }
    }
    __syncthreads();   // all s_part written

    // ---- combine quarter-sums + bias --------------------------------------
    const float bsc = bscore[0];
    for (int idx = tid; idx < QT * S_ENC; idx += ATH) {
        const int qq = idx >> 8, e = idx & (S_ENC - 1);
        s_sc[qq * S_ENC + e] =
            s_part[(4 * qq + 0) * S_ENC + e] + s_part[(4 * qq + 1) * S_ENC + e] +
            s_part[(4 * qq + 2) * S_ENC + e] + s_part[(4 * qq + 3) * S_ENC + e] + bsc;
    }
    __syncthreads();

    // ---- softmax (warps 0-7 handle q=w); write transposed [e][q] ----------
    if (w < QT) {
        float v[S_ENC / 32];
        float m = -1e30f;
        #pragma unroll
        for (int i = 0; i < S_ENC / 32; i++) {
            v[i] = s_sc[w * S_ENC + lane + 32 * i];
            m = fmaxf(m, v[i]);
        }
        #pragma unroll
        for (int off = 16; off; off >>= 1)
            m = fmaxf(m, __shfl_xor_sync(0xFFFFFFFFu, m, off));
        float sum = 0.f;
        #pragma unroll
        for (int i = 0; i < S_ENC / 32; i++) {
            v[i] = __expf(v[i] - m);
            sum += v[i];
        }
        #pragma unroll
        for (int off = 16; off; off >>= 1)
            sum += __shfl_xor_sync(0xFFFFFFFFu, sum, off);
        const float inv = 1.f / sum;
        #pragma unroll
        for (int i = 0; i < S_ENC / 32; i++)
            s_t[(lane + 32 * i) * QT + w] = v[i] * inv;
    }
    __syncthreads();

    // ---- context: warp w owns dims [w*16, w*16+16); half-warps split e ----
    const int dl = lane & 15;
    const int eh = lane >> 4;           // 0/1 -> e-half
    const int d0 = w * 16 + dl;
    float c[QT] = {};
    const float* ep = enc + b * S_ENC * DIM;

    const int e_beg = eh * 128;
    #pragma unroll 4
    for (int e = e_beg; e < e_beg + 128; e++) {
        const float ev = ep[e * DIM + d0];
        const float4 w0 = *(const float4*)&s_t[e * QT];       // broadcast
        const float4 w1 = *(const float4*)&s_t[e * QT + 4];
        c[0] = fmaf(w0.x, ev, c[0]);
        c[1] = fmaf(w0.y, ev, c[1]);
        c[2] = fmaf(w0.z, ev, c[2]);
        c[3] = fmaf(w0.w, ev, c[3]);
        c[4] = fmaf(w1.x, ev, c[4]);
        c[5] = fmaf(w1.y, ev, c[5]);
        c[6] = fmaf(w1.z, ev, c[6]);
        c[7] = fmaf(w1.w, ev, c[7]);
    }
    #pragma unroll
    for (int qq = 0; qq < QT; qq++)
        c[qq] += __shfl_xor_sync(0xFFFFFFFFu, c[qq], 16);

    if (lane < 16) {
        #pragma unroll
        for (int qq = 0; qq < QT; qq++)
            out[(b * S_DEC + q0 + qq) * DIM + d0] = c[qq];
    }
}

#define ATTN_SMEM ((2 * EB * DIM + 32 * S_ENC + 2 * QT * S_ENC) * (int)sizeof(float))

// ---------------------------------------------------------------------------
extern "C" void kernel_launch(void* const* d_in, const int* in_sizes, int n_in,
                              void* d_out, int out_size)
{
    const float* encodings = (const float*)d_in[0];   // [8,256,512]
    const float* decodings = (const float*)d_in[1];   // [8,128,512]
    const float* W_enc     = (const float*)d_in[2];   // [512,512]
    const float* W_dec     = (const float*)d_in[3];   // [512,512]
    const float* W_score   = (const float*)d_in[4];   // [512,1]
    const float* bias_enc  = (const float*)d_in[5];   // [512]
    const float* bias_dec  = (const float*)d_in[6];   // [512]
    const float* bias_sc   = (const float*)d_in[7];   // [1]
    float* out = (float*)d_out;                       // [8,128,512]

    void* p_tenc = nullptr;
    void* p_tdec = nullptr;
    cudaGetSymbolAddress(&p_tenc, g_tenc);
    cudaGetSymbolAddress(&p_tdec, g_tdec);

    cudaFuncSetAttribute(attn_kernel,
                         cudaFuncAttributeMaxDynamicSharedMemorySize, ATTN_SMEM);

    // both projections (with tanh epilogue) in one tensor-core launch
    {
        dim3 grid(DIM / TBN, (NB * S_ENC) / TBM, 2);   // (8, 32, 2)
        gemm_tf32_kernel<<<grid, 128>>>(encodings, W_enc, bias_enc,
                                        (float*)p_tenc,
                                        decodings, W_dec, bias_dec,
                                        (float*)p_tdec);
    }

    // scores + softmax + context
    {
        dim3 grid(S_DEC / QT, NB);                     // (16, 8)
        attn_kernel<<<grid, ATH, ATTN_SMEM>>>(encodings, W_score, bias_sc, out);
    }
}

// round 16
// speedup vs baseline: 1.3523x; 1.1719x over previous
#include <cuda_runtime.h>
#include <cstdint>

#define NB     8
#define S_ENC  256
#define S_DEC  128
#define DIM    512     // D_ENC = D_DEC = UNITS = 512

// Scratch (no cudaMalloc allowed): tanh-transformed projections
__device__ float g_tenc[NB * S_ENC * DIM];   // tanh(enc @ W_enc + b_enc)
__device__ float g_tdec[NB * S_DEC * DIM];   // tanh(dec @ W_dec + b_dec)

__device__ __forceinline__ float tanh_approx(float x) {
    float y;
    asm("tanh.approx.f32 %0, %1;" : "=f"(y) : "f"(x));
    return y;
}

// ---------------------------------------------------------------------------
// tf32 tensor-core GEMM (3xTF32 split -> fp32-level accuracy), tanh epilogue.
// ---------------------------------------------------------------------------
#define TBM 64
#define TBN 64
#define TBK 32
#define ASTR 36
#define BSTR 72
#define NC  (DIM / TBK)

__device__ __forceinline__ uint32_t f2tf32(float x) {
    uint32_t u;
    asm("cvt.rna.tf32.f32 %0, %1;" : "=r"(u) : "f"(x));
    return u;
}
__device__ __forceinline__ void split_tf32(float x, uint32_t& hi, uint32_t& lo) {
    hi = f2tf32(x);
    lo = f2tf32(x - __uint_as_float(hi));
}
__device__ __forceinline__ void mma_tf32(float c[4], const uint32_t a[4],
                                         const uint32_t b[2]) {
    asm volatile(
        "mma.sync.aligned.m16n8k8.row.col.f32.tf32.tf32.f32 "
        "{%0,%1,%2,%3}, {%4,%5,%6,%7}, {%8,%9}, {%0,%1,%2,%3};"
        : "+f"(c[0]), "+f"(c[1]), "+f"(c[2]), "+f"(c[3])
        : "r"(a[0]), "r"(a[1]), "r"(a[2]), "r"(a[3]), "r"(b[0]), "r"(b[1]));
}

__global__ __launch_bounds__(128) void gemm_tf32_kernel(
    const float* __restrict__ Xe, const float* __restrict__ We,
    const float* __restrict__ be, float* __restrict__ Ce,
    const float* __restrict__ Xd, const float* __restrict__ Wd,
    const float* __restrict__ bd, float* __restrict__ Cd)
{
    const int z = blockIdx.z;
    if (z == 1 && blockIdx.y >= (NB * S_DEC) / TBM) return;

    const float* __restrict__ X    = z ? Xd : Xe;
    const float* __restrict__ W    = z ? Wd : We;
    const float* __restrict__ bias = z ? bd : be;
    float* __restrict__ C          = z ? Cd : Ce;

    __shared__ float As[2][TBM * ASTR];
    __shared__ float Bs[2][TBK * BSTR];
    __shared__ float bsm[TBN];

    const int tid  = threadIdx.x;
    const int lane = tid & 31;
    const int warp = tid >> 5;
    const int wm   = warp >> 1;
    const int wn   = warp & 1;
    const int row0 = blockIdx.y * TBM;
    const int col0 = blockIdx.x * TBN;

    if (tid < TBN) bsm[tid] = bias[col0 + tid];

    #define ISSUE_GEMM_CHUNK(ch, st)                                           \
        do {                                                                   \
            const int k0 = (ch) * TBK;                                         \
            _Pragma("unroll")                                                  \
            for (int j = 0; j < 4; j++) {                                      \
                const int idx = j * 128 + tid;                                 \
                const int r = idx >> 3, c = (idx & 7) * 4;                     \
                const unsigned dst = (unsigned)__cvta_generic_to_shared(       \
                    &As[st][r * ASTR + c]);                                    \
                const float* src = &X[(row0 + r) * DIM + k0 + c];              \
                asm volatile("cp.async.cg.shared.global [%0], [%1], 16;\n"     \
                             :: "r"(dst), "l"(src));                           \
            }                                                                  \
            _Pragma("unroll")                                                  \
            for (int j = 0; j < 4; j++) {                                      \
                const int idx = j * 128 + tid;                                 \
                const int r = idx >> 4, c = (idx & 15) * 4;                    \
                const unsigned dst = (unsigned)__cvta_generic_to_shared(       \
                    &Bs[st][r * BSTR + c]);                                    \
                const float* src = &W[(k0 + r) * DIM + col0 + c];              \
                asm volatile("cp.async.cg.shared.global [%0], [%1], 16;\n"     \
                             :: "r"(dst), "l"(src));                           \
            }                                                                  \
            asm volatile("cp.async.commit_group;\n");                          \
        } while (0)

    float acc[2][4][4] = {};

    ISSUE_GEMM_CHUNK(0, 0);
    ISSUE_GEMM_CHUNK(1, 1);
    asm volatile("cp.async.wait_group 1;\n");
    __syncthreads();

    for (int ch = 0; ch < NC; ch++) {
        const int st = ch & 1;
        const float* A = As[st];
        const float* B = Bs[st];

        #pragma unroll
        for (int ks = 0; ks < TBK / 8; ks++) {
            const int k = ks * 8;
            uint32_t ahi[2][4], alo[2][4];
            #pragma unroll
            for (int mt = 0; mt < 2; mt++) {
                const int m = wm * 32 + mt * 16;
                const int r = m + (lane >> 2);
                const int c = k + (lane & 3);
                split_tf32(A[r * ASTR + c],           ahi[mt][0], alo[mt][0]);
                split_tf32(A[(r + 8) * ASTR + c],     ahi[mt][1], alo[mt][1]);
                split_tf32(A[r * ASTR + c + 4],       ahi[mt][2], alo[mt][2]);
                split_tf32(A[(r + 8) * ASTR + c + 4], ahi[mt][3], alo[mt][3]);
            }
            uint32_t bhi[4][2], blo[4][2];
            #pragma unroll
            for (int nt = 0; nt < 4; nt++) {
                const int n = wn * 32 + nt * 8 + (lane >> 2);
                const int r = k + (lane & 3);
                split_tf32(B[r * BSTR + n],       bhi[nt][0], blo[nt][0]);
                split_tf32(B[(r + 4) * BSTR + n], bhi[nt][1], blo[nt][1]);
            }
            #pragma unroll
            for (int mt = 0; mt < 2; mt++)
                #pragma unroll
                for (int nt = 0; nt < 4; nt++) {
                    mma_tf32(acc[mt][nt], ahi[mt], bhi[nt]);
                    mma_tf32(acc[mt][nt], ahi[mt], blo[nt]);
                    mma_tf32(acc[mt][nt], alo[mt], bhi[nt]);
                }
        }

        __syncthreads();
        if (ch + 2 < NC) {
            ISSUE_GEMM_CHUNK(ch + 2, st);
            asm volatile("cp.async.wait_group 1;\n");
            __syncthreads();
        } else if (ch + 1 < NC) {
            asm volatile("cp.async.wait_group 0;\n");
            __syncthreads();
        }
    }

    // ---- epilogue: bias + tanh + store ------------------------------------
    #pragma unroll
    for (int mt = 0; mt < 2; mt++) {
        const int r = row0 + wm * 32 + mt * 16 + (lane >> 2);
        #pragma unroll
        for (int nt = 0; nt < 4; nt++) {
            const int cl = wn * 32 + nt * 8 + (lane & 3) * 2;
            const float b0 = bsm[cl], b1 = bsm[cl + 1];
            float2 v0 = {tanh_approx(acc[mt][nt][0] + b0),
                         tanh_approx(acc[mt][nt][1] + b1)};
            float2 v1 = {tanh_approx(acc[mt][nt][2] + b0),
                         tanh_approx(acc[mt][nt][3] + b1)};
            *(float2*)&C[r * DIM + col0 + cl]       = v0;
            *(float2*)&C[(r + 8) * DIM + col0 + cl] = v1;
        }
    }
}

// ---------------------------------------------------------------------------
// Attention kernel. Block = (batch b, QT=8 q's), 1024 threads = 32 warps.
// Warp w -> (q = w>>2, u-quarter = w&3); lane owns 4 contiguous u.
// Inner loop (tanh addition formula, ws folded into the numerator):
//   term_u = ws*(td+te)/(1+td*te), with n = fma(ws,te,ws*td), d = fma(td,te,1)
// n/d computed via PACKED fma.rn.f32x2 (4 packed FMA = 8 scalar FMAs in 8
// fma-pipe cycles), fractions combined pairwise so only 2 RCP per e.
// Per-e budget: 12 fma-pipe slots (24 cyc), 2 XU (16 cyc).
// ---------------------------------------------------------------------------
#define QT   8
#define EB   16                  // encoder rows per chunk
#define NCH  (S_ENC / EB)        // 16
#define ATH  1024
#define CHV  (EB * DIM / 4)      // 2048 float4 per chunk
#define PFT  (CHV / ATH)         // 2 float4 per thread

__device__ __forceinline__ uint64_t pack2(float lo, float hi) {
    uint64_t r;
    asm("mov.b64 %0, {%1, %2};" : "=l"(r) : "f"(lo), "f"(hi));
    return r;
}
// packed f32x2 FMA with unpacked float outputs (mov.b64 split = reg aliasing)
#define FMA2(o_lo, o_hi, a, b, c)                                              \
    asm("{.reg .b64 t; fma.rn.f32x2 t, %2, %3, %4; mov.b64 {%0, %1}, t;}"      \
        : "=f"(o_lo), "=f"(o_hi) : "l"(a), "l"(b), "l"(c))

__global__ __launch_bounds__(ATH, 1) void attn_kernel(
    const float* __restrict__ enc,      // [B, S_ENC, DIM] raw encodings
    const float* __restrict__ wscore,   // [DIM]
    const float* __restrict__ bscore,   // [1]
    float* __restrict__ out)            // [B, S_DEC, DIM]
{
    extern __shared__ float smem[];
    float* s_de   = smem;                         // 2*EB*DIM   (16384 f)
    float* s_part = s_de + 2 * EB * DIM;          // 32*S_ENC   (8192 f)
    float* s_sc   = s_part + 32 * S_ENC;          // QT*S_ENC   (2048 f)
    float* s_t    = s_sc + QT * S_ENC;            // S_ENC*QT   (2048 f)

    const int b    = blockIdx.y;
    const int q0   = blockIdx.x * QT;
    const int tid  = threadIdx.x;
    const int lane = tid & 31;
    const int w    = tid >> 5;
    const int q    = w >> 2;            // local q in [0,8)
    const int quad = w & 3;             // u-quarter
    const int u0   = quad * 128 + lane * 4;   // 4 contiguous u per lane

    // ---- loop-invariant packed registers ----------------------------------
    uint64_t td01, td23, ws01, ws23, wtd01, wtd23;
    const uint64_t ONE2 = 0x3F8000003F800000ULL;
    {
        const float* tdp = g_tdec + (b * S_DEC + q0 + q) * DIM;
        const float4 td = *(const float4*)&tdp[u0];
        const float4 ws = *(const float4*)&wscore[u0];
        td01 = pack2(td.x, td.y);
        td23 = pack2(td.z, td.w);
        ws01 = pack2(ws.x, ws.y);
        ws23 = pack2(ws.z, ws.w);
        wtd01 = pack2(ws.x * td.x, ws.y * td.y);
        wtd23 = pack2(ws.z * td.z, ws.w * td.w);
    }

    const float4* gsrc = (const float4*)(g_tenc + b * S_ENC * DIM);
    const unsigned sde_base = (unsigned)__cvta_generic_to_shared(s_de);

    #define ISSUE_CHUNK(ch, buf)                                               \
        do {                                                                   \
            _Pragma("unroll")                                                  \
            for (int j = 0; j < PFT; j++) {                                    \
                const int idx = j * ATH + tid;                                 \
                const unsigned dst = sde_base + ((buf) * CHV + idx) * 16u;     \
                const float4* srcp = gsrc + (ch) * CHV + idx;                  \
                asm volatile("cp.async.cg.shared.global [%0], [%1], 16;\n"     \
                             :: "r"(dst), "l"(srcp));                          \
            }                                                                  \
            asm volatile("cp.async.commit_group;\n");                          \
        } while (0)

    ISSUE_CHUNK(0, 0);
    ISSUE_CHUNK(1, 1);
    asm volatile("cp.async.wait_group 1;\n");
    __syncthreads();

    // ---- score chunks ------------------------------------------------------
    for (int ch = 0; ch < NCH; ch++) {
        const ulonglong2* de8 =
            (const ulonglong2*)(s_de + (ch & 1) * EB * DIM) + (u0 >> 2);

        float acc[EB];
        #pragma unroll
        for (int e = 0; e < EB; e++) {
            const ulonglong2 tev = de8[e * (DIM / 4)];
            float n0, n1, n2, n3, d0, d1, d2, d3;
            FMA2(n0, n1, ws01, tev.x, wtd01);
            FMA2(d0, d1, td01, tev.x, ONE2);
            FMA2(n2, n3, ws23, tev.y, wtd23);
            FMA2(d2, d3, td23, tev.y, ONE2);
            // pairwise fraction combine: 2 RCP per e
            float num0 = n0 * d1;  num0 = fmaf(n1, d0, num0);
            float den0 = d0 * d1;
            float num1 = n2 * d3;  num1 = fmaf(n3, d2, num1);
            float den1 = d2 * d3;
            float r0, r1;
            asm("rcp.approx.f32 %0, %1;" : "=f"(r0) : "f"(den0));
            asm("rcp.approx.f32 %0, %1;" : "=f"(r1) : "f"(den1));
            const float t = num0 * r0;
            acc[e] = fmaf(num1, r1, t);
        }

        // multi-value butterfly: fold 16 values over stages s=16..2, then s=1
        #pragma unroll
        for (int s = 16, n = 8; s >= 2; s >>= 1, n >>= 1) {
            const bool hi = (lane & s) != 0;
            #pragma unroll
            for (int j = 0; j < n; j++) {
                const float send = hi ? acc[j] : acc[j + n];
                const float keep = hi ? acc[j + n] : acc[j];
                acc[j] = keep + __shfl_xor_sync(0xFFFFFFFFu, send, s);
            }
        }
        acc[0] += __shfl_xor_sync(0xFFFFFFFFu, acc[0], 1);
        if ((lane & 1) == 0)
            s_part[w * S_ENC + ch * EB + ((lane >> 1) & 15)] = acc[0];

        if (ch + 1 < NCH) {
            __syncthreads();                       // done reading buf[ch&1]
            if (ch + 2 < NCH) {
                ISSUE_CHUNK(ch + 2, (ch & 1));
                asm volatile("cp.async.wait_group 1;\n");
            } else {
                asm volatile("cp.async.wait_group 0;\n");
            }
            __syncthreads();                       // new buffer visible
        }
    }
    __syncthreads();   // all s_part written

    // ---- combine quarter-sums + bias --------------------------------------
    const float bsc = bscore[0];
    for (int idx = tid; idx < QT * S_ENC; idx += ATH) {
        const int qq = idx >> 8, e = idx & (S_ENC - 1);
        s_sc[qq * S_ENC + e] =
            s_part[(4 * qq + 0) * S_ENC + e] + s_part[(4 * qq + 1) * S_ENC + e] +
            s_part[(4 * qq + 2) * S_ENC + e] + s_part[(4 * qq + 3) * S_ENC + e] + bsc;
    }
    __syncthreads();

    // ---- softmax (warps 0-7 handle q=w); write transposed [e][q] ----------
    if (w < QT) {
        float v[S_ENC / 32];
        float m = -1e30f;
        #pragma unroll
        for (int i = 0; i < S_ENC / 32; i++) {
            v[i] = s_sc[w * S_ENC + lane + 32 * i];
            m = fmaxf(m, v[i]);
        }
        #pragma unroll
        for (int off = 16; off; off >>= 1)
            m = fmaxf(m, __shfl_xor_sync(0xFFFFFFFFu, m, off));
        float sum = 0.f;
        #pragma unroll
        for (int i = 0; i < S_ENC / 32; i++) {
            v[i] = __expf(v[i] - m);
            sum += v[i];
        }
        #pragma unroll
        for (int off = 16; off; off >>= 1)
            sum += __shfl_xor_sync(0xFFFFFFFFu, sum, off);
        const float inv = 1.f / sum;
        #pragma unroll
        for (int i = 0; i < S_ENC / 32; i++)
            s_t[(lane + 32 * i) * QT + w] = v[i] * inv;
    }
    __syncthreads();

    // ---- context: warp w owns dims [w*16, w*16+16); half-warps split e ----
    const int dl = lane & 15;
    const int eh = lane >> 4;           // 0/1 -> e-half
    const int d0 = w * 16 + dl;
    float c[QT] = {};
    const float* ep = enc + b * S_ENC * DIM;

    const int e_beg = eh * 128;
    #pragma unroll 4
    for (int e = e_beg; e < e_beg + 128; e++) {
        const float ev = ep[e * DIM + d0];
        const float4 w0 = *(const float4*)&s_t[e * QT];       // broadcast
        const float4 w1 = *(const float4*)&s_t[e * QT + 4];
        c[0] = fmaf(w0.x, ev, c[0]);
        c[1] = fmaf(w0.y, ev, c[1]);
        c[2] = fmaf(w0.z, ev, c[2]);
        c[3] = fmaf(w0.w, ev, c[3]);
        c[4] = fmaf(w1.x, ev, c[4]);
        c[5] = fmaf(w1.y, ev, c[5]);
        c[6] = fmaf(w1.z, ev, c[6]);
        c[7] = fmaf(w1.w, ev, c[7]);
    }
    #pragma unroll
    for (int qq = 0; qq < QT; qq++)
        c[qq] += __shfl_xor_sync(0xFFFFFFFFu, c[qq], 16);

    if (lane < 16) {
        #pragma unroll
        for (int qq = 0; qq < QT; qq++)
            out[(b * S_DEC + q0 + qq) * DIM + d0] = c[qq];
    }
}

#define ATTN_SMEM ((2 * EB * DIM + 32 * S_ENC + 2 * QT * S_ENC) * (int)sizeof(float))

// ---------------------------------------------------------------------------
extern "C" void kernel_launch(void* const* d_in, const int* in_sizes, int n_in,
                              void* d_out, int out_size)
{
    const float* encodings = (const float*)d_in[0];   // [8,256,512]
    const float* decodings = (const float*)d_in[1];   // [8,128,512]
    const float* W_enc     = (const float*)d_in[2];   // [512,512]
    const float* W_dec     = (const float*)d_in[3];   // [512,512]
    const float* W_score   = (const float*)d_in[4];   // [512,1]
    const float* bias_enc  = (const float*)d_in[5];   // [512]
    const float* bias_dec  = (const float*)d_in[6];   // [512]
    const float* bias_sc   = (const float*)d_in[7];   // [1]
    float* out = (float*)d_out;                       // [8,128,512]

    void* p_tenc = nullptr;
    void* p_tdec = nullptr;
    cudaGetSymbolAddress(&p_tenc, g_tenc);
    cudaGetSymbolAddress(&p_tdec, g_tdec);

    cudaFuncSetAttribute(attn_kernel,
                         cudaFuncAttributeMaxDynamicSharedMemorySize, ATTN_SMEM);

    // both projections (with tanh epilogue) in one tensor-core launch
    {
        dim3 grid(DIM / TBN, (NB * S_ENC) / TBM, 2);   // (8, 32, 2)
        gemm_tf32_kernel<<<grid, 128>>>(encodings, W_enc, bias_enc,
                                        (float*)p_tenc,
                                        decodings, W_dec, bias_dec,
                                        (float*)p_tdec);
    }

    // scores + softmax + context
    {
        dim3 grid(S_DEC / QT, NB);                     // (16, 8)
        attn_kernel<<<grid, ATH, ATTN_SMEM>>>(encodings, W_score, bias_sc, out);
    }
}